// round 7
// baseline (speedup 1.0000x reference)
#include <cuda_runtime.h>
#include <math.h>
#include <stdint.h>

#define NEARV     2.0f
#define FARV      6.0f
#define FAR_DIST  1e10f
#define S         128
#define TPB       64           // threads = rays per block
#define CS        8            // samples per chunk
#define NCHUNK    (S / CS)     // 16
#define STAGES    3
#define MAX_BLK   16384
#define FULL      0xffffffffu

// Deterministic scratch for the fused scalar reduction (no allocations allowed).
__device__ float        g_partials[MAX_BLK];
__device__ unsigned int g_count = 0;

__device__ __forceinline__ void cp_async16(uint32_t dst, const void* src) {
    asm volatile("cp.async.cg.shared.global [%0], [%1], 16;" :: "r"(dst), "l"(src));
}
__device__ __forceinline__ void cp_commit() {
    asm volatile("cp.async.commit_group;");
}
template<int W> __device__ __forceinline__ void cp_wait() {
    asm volatile("cp.async.wait_group %0;" :: "n"(W));
}

__global__ __launch_bounds__(TPB) void integrate_kernel(
    const float* __restrict__ raw,     // [N, S, 4]
    const float* __restrict__ zvals,   // [N, S]
    const float* __restrict__ rays_d,  // [N, 3]
    float* __restrict__ out,           // [3N chs | N depth | 1 scalar]
    int N)
{
    // sample-major staging: reads are lane-contiguous LDS.128, conflict-free
    __shared__ float4 raw_s[STAGES][CS][TPB];        // 3*8*64*16 = 24 KB
    __shared__ float4 z_s[STAGES][CS / 4][TPB];      // 3*2*64*16 =  6 KB
    __shared__ float  sh_ent[TPB / 32];
    __shared__ double sh_red[TPB];
    __shared__ bool   sh_last;

    const int t   = threadIdx.x;
    const int r0  = blockIdx.x * TPB;
    const int ray = r0 + t;
    const bool active = (ray < N);

    float nrm = 0.0f;
    if (active) {
        const float* rd = rays_d + (size_t)ray * 3;
        nrm = sqrtf(rd[0] * rd[0] + rd[1] * rd[1] + rd[2] * rd[2]);
    }

    const float4* rp4 = (const float4*)raw;     // global float4 index: ray*S + j
    const float4* zp4 = (const float4*)zvals;   // global float4 index: ray*(S/4) + jb

    // ---- chunk issue: gmem-coalesced cp.async into sample-major smem ----
    auto issue = [&](int c, int s) {
        const int jj = t & 7, rb = t >> 3;               // 8 f4 per thread (raw)
        #pragma unroll
        for (int k = 0; k < 8; k++) {
            const int rl = rb + 8 * k;
            if (r0 + rl < N)
                cp_async16((uint32_t)__cvta_generic_to_shared(&raw_s[s][jj][rl]),
                           rp4 + (size_t)(r0 + rl) * S + c * CS + jj);
        }
        const int jb = t & 1, rz = t >> 1;               // 2 f4 per thread (z)
        #pragma unroll
        for (int k = 0; k < 2; k++) {
            const int rl = rz + 32 * k;
            if (r0 + rl < N)
                cp_async16((uint32_t)__cvta_generic_to_shared(&z_s[s][jb][rl]),
                           zp4 + (size_t)(r0 + rl) * (S / 4) + c * (CS / 4) + jb);
        }
    };

    // prologue: fill STAGES-1 stages
    #pragma unroll
    for (int p = 0; p < STAGES - 1; p++) { issue(p, p); cp_commit(); }

    // serial per-ray state (one-sample lag; dummy first sample is a no-op)
    float T = 1.0f, c0 = 0.f, c1 = 0.f, c2 = 0.f, dn = 0.f, ws = 0.f, S1 = 0.f;
    float rx = 0.f, ry = 0.f, rz_ = 0.f, sig_p = -1.0f, zp = 0.0f;

    for (int c = 0; c < NCHUNK; c++) {
        cp_wait<STAGES - 2>();
        __syncthreads();                       // chunk c visible to all; stage (c-1)%STAGES free

        const int cn = c + STAGES - 1;         // refill freed stage
        if (cn < NCHUNK) issue(cn, cn % STAGES);
        cp_commit();                           // one commit per iteration (group accounting)

        if (active) {
            const int s = c % STAGES;
            float4 z4;
            #pragma unroll
            for (int jj = 0; jj < CS; jj++) {
                if ((jj & 3) == 0) z4 = z_s[s][jj >> 2][t];
                const float zc = ((jj & 3) == 0) ? z4.x :
                                 ((jj & 3) == 1) ? z4.y :
                                 ((jj & 3) == 2) ? z4.z : z4.w;
                const float4 rc = raw_s[s][jj][t];

                // finish previous sample with dist = z[j] - z[j-1]
                const float dist = (zc - zp) * nrm;
                const float e  = __expf(-fmaxf(sig_p, 0.0f) * dist);
                const float w  = (1.0f - e) * T;
                c0 += w * rx;  c1 += w * ry;  c2 += w * rz_;
                dn += w * (FARV - zp) * 0.25f;     // 1/(FAR-NEAR)
                ws += w;
                if (w > 0.0f) S1 += w * __logf(w);
                T *= (e + 1e-10f);

                rx = rc.x; ry = rc.y; rz_ = rc.z; sig_p = rc.w; zp = zc;
            }
        }
    }

    float ent = 0.0f;
    if (active) {
        // last sample: dist = FAR_DIST
        const float dist = FAR_DIST * nrm;
        const float e  = __expf(-fmaxf(sig_p, 0.0f) * dist);
        const float w  = (1.0f - e) * T;
        c0 += w * rx;  c1 += w * ry;  c2 += w * rz_;
        dn += w * (FARV - zp) * 0.25f;
        ws += w;
        if (w > 0.0f) S1 += w * __logf(w);

        out[(size_t)ray * 3 + 0] = c0;
        out[(size_t)ray * 3 + 1] = c1;
        out[(size_t)ray * 3 + 2] = c2;
        out[(size_t)3 * N + ray] = dn / (ws + 1e-5f);

        // sum p*ln p  (p = w/(1+1e-6)):  invD*(S1 + ln(invD)*ws) + tail term
        const float invD = 1.0f / (1.0f + 1e-6f);
        ent = invD * (S1 + (-9.999995e-7f) * ws);
        const float p_last = (1.0f - ws + 1e-6f) * invD;
        if (p_last > 0.0f) ent += p_last * __logf(p_last);
    }

    // ---- entropy: warp + block + fused deterministic grid reduction ----
    #pragma unroll
    for (int off = 16; off > 0; off >>= 1)
        ent += __shfl_down_sync(FULL, ent, off);
    if ((t & 31) == 0) sh_ent[t >> 5] = ent;
    __syncthreads();

    if (t == 0) {
        g_partials[blockIdx.x] = sh_ent[0] + sh_ent[1];
        __threadfence();
        const unsigned int done = atomicAdd(&g_count, 1u);
        sh_last = (done == gridDim.x - 1);
    }
    __syncthreads();

    if (sh_last) {
        double s = 0.0;
        for (int i = t; i < (int)gridDim.x; i += TPB)
            s += (double)g_partials[i];
        sh_red[t] = s;
        __syncthreads();
        #pragma unroll
        for (int off = TPB / 2; off > 0; off >>= 1) {
            if (t < off) sh_red[t] += sh_red[t + off];
            __syncthreads();
        }
        if (t == 0) {
            out[(size_t)4 * N] = (float)(-sh_red[0]);   // sparsity_loss
            g_count = 0;                                 // re-arm for next replay
        }
    }
}

extern "C" void kernel_launch(void* const* d_in, const int* in_sizes, int n_in,
                              void* d_out, int out_size)
{
    const float* raw    = (const float*)d_in[0];
    const float* zvals  = (const float*)d_in[1];
    const float* rays_d = (const float*)d_in[2];
    float* out = (float*)d_out;

    const int N = in_sizes[2] / 3;               // rays_d is [N,3]
    const int blocks = (N + TPB - 1) / TPB;

    integrate_kernel<<<blocks, TPB>>>(raw, zvals, rays_d, out, N);
}

// round 8
// speedup vs baseline: 1.3478x; 1.3478x over previous
#include <cuda_runtime.h>
#include <math.h>

#define NEARV     2.0f
#define FARV      6.0f
#define FAR_DIST  1e10f
#define S         128
#define TPB       128          // 4 warps, 8 rays per block
#define MAX_BLK   16384
#define FULL      0xffffffffu

// Deterministic scratch for the fused scalar reduction (no allocations allowed).
__device__ float        g_partials[MAX_BLK];
__device__ unsigned int g_count = 0;

__global__ __launch_bounds__(TPB) void integrate_kernel(
    const float* __restrict__ raw,     // [N, S, 4]
    const float* __restrict__ zvals,   // [N, S]
    const float* __restrict__ rays_d,  // [N, 3]
    float* __restrict__ out,           // [3N chs | N depth | 1 scalar]
    int N)
{
    __shared__ float  sh_ent[TPB / 32];
    __shared__ double sh_red[TPB];
    __shared__ bool   sh_last;

    const int warp = threadIdx.x >> 5;
    const int lane = threadIdx.x & 31;
    const int half = lane >> 4;              // 0 -> ray A, 1 -> ray B
    const int l    = lane & 15;              // lane within ray group
    const int ray  = (blockIdx.x * (TPB >> 5) + warp) * 2 + half;
    const bool active = (ray < N);

    // ---- coalesced loads: lane owns samples j = 16k + l, k = 0..7 ----
    float4 r[8];
    float  zn[8], a[8], t[8];
    {
        const float4* rp = (const float4*)raw + (active ? (size_t)ray * S : 0);
        const float*  zp = zvals + (active ? (size_t)ray * S : 0);

        float nrm = 0.0f;
        if (active) {
            const float* rd = rays_d + (size_t)ray * 3;
            nrm = sqrtf(rd[0] * rd[0] + rd[1] * rd[1] + rd[2] * rd[2]);
        }

        #pragma unroll
        for (int k = 0; k < 8; k++) r[k] = rp[16 * k + l];

        #pragma unroll
        for (int k = 0; k < 8; k++) {
            const int j  = 16 * k + l;
            const float z    = zp[j];
            const float znxt = zp[(j + 1 < S) ? j + 1 : (S - 1)];  // same lines, L1
            float dist = (j == S - 1) ? FAR_DIST : (znxt - z);
            dist *= nrm;
            const float sig = active ? r[k].w : -1.0f;
            const float e = __expf(-fmaxf(sig, 0.0f) * dist);
            a[k]  = 1.0f - e;
            t[k]  = e + 1e-10f;
            zn[k] = (FARV - z) * 0.25f;          // 1/(FAR-NEAR)
        }
    }

    // ---- 8 segmented (width-16) inclusive multiplicative scans ----
    #pragma unroll
    for (int off = 1; off < 16; off <<= 1) {
        #pragma unroll
        for (int k = 0; k < 8; k++) {
            const float v = __shfl_up_sync(FULL, t[k], off, 16);
            if (l >= off) t[k] *= v;
        }
    }

    // exclusive scans + slab totals (t[k] now = inclusive scan sc)
    float excl[8], P[8];
    #pragma unroll
    for (int k = 0; k < 8; k++) {
        const float e = __shfl_up_sync(FULL, t[k], 1, 16);
        excl[k] = (l == 0) ? 1.0f : e;
        P[k]    = __shfl_sync(FULL, t[k], 15, 16);
    }

    // ---- weights & accumulation; entropy as S1 = sum w*ln(w) ----
    float c0 = 0.f, c1 = 0.f, c2 = 0.f, dn = 0.f, ws = 0.f, S1 = 0.f;
    float Ck = 1.0f;
    #pragma unroll
    for (int k = 0; k < 8; k++) {
        const float w = a[k] * (Ck * excl[k]);
        c0 += w * r[k].x;
        c1 += w * r[k].y;
        c2 += w * r[k].z;
        dn += w * zn[k];
        ws += w;
        if (w > 0.0f) S1 += w * __logf(w);
        Ck *= P[k];
    }

    // ---- segmented (width-16) reductions: results in lanes 0 and 16 ----
    #pragma unroll
    for (int off = 8; off > 0; off >>= 1) {
        c0 += __shfl_down_sync(FULL, c0, off, 16);
        c1 += __shfl_down_sync(FULL, c1, off, 16);
        c2 += __shfl_down_sync(FULL, c2, off, 16);
        dn += __shfl_down_sync(FULL, dn, off, 16);
        ws += __shfl_down_sync(FULL, ws, off, 16);
        S1 += __shfl_down_sync(FULL, S1, off, 16);
    }

    float ent = 0.0f;
    if (l == 0 && active) {
        out[(size_t)ray * 3 + 0] = c0;
        out[(size_t)ray * 3 + 1] = c1;
        out[(size_t)ray * 3 + 2] = c2;
        out[(size_t)3 * N + ray] = dn / (ws + 1e-5f);
        // sum p*ln p  (p = w/(1+1e-6)) = invD*(S1 + ln(invD)*ws) + tail
        const float invD = 1.0f / (1.0f + 1e-6f);
        ent = invD * (S1 + (-9.999995e-7f) * ws);
        const float p_last = (1.0f - ws + 1e-6f) * invD;
        if (p_last > 0.0f) ent += p_last * __logf(p_last);
    }
    // combine the two per-ray entropies into lane 0
    ent += __shfl_down_sync(FULL, ent, 16);

    // warp partial -> shared
    if (lane == 0) sh_ent[warp] = ent;
    __syncthreads();

    // ---- fused deterministic grid reduction (threadfence-reduction pattern) ----
    if (threadIdx.x == 0) {
        float s = 0.0f;
        #pragma unroll
        for (int w = 0; w < TPB / 32; w++) s += sh_ent[w];
        g_partials[blockIdx.x] = s;
        __threadfence();
        const unsigned int done = atomicAdd(&g_count, 1u);
        sh_last = (done == gridDim.x - 1);
    }
    __syncthreads();

    if (sh_last) {
        double s = 0.0;
        for (int i = threadIdx.x; i < (int)gridDim.x; i += TPB)
            s += (double)g_partials[i];
        sh_red[threadIdx.x] = s;
        __syncthreads();
        #pragma unroll
        for (int off = TPB / 2; off > 0; off >>= 1) {
            if (threadIdx.x < off) sh_red[threadIdx.x] += sh_red[threadIdx.x + off];
            __syncthreads();
        }
        if (threadIdx.x == 0) {
            out[(size_t)4 * N] = (float)(-sh_red[0]);   // sparsity_loss
            g_count = 0;                                 // re-arm for next replay
        }
    }
}

extern "C" void kernel_launch(void* const* d_in, const int* in_sizes, int n_in,
                              void* d_out, int out_size)
{
    const float* raw    = (const float*)d_in[0];
    const float* zvals  = (const float*)d_in[1];
    const float* rays_d = (const float*)d_in[2];
    float* out = (float*)d_out;

    const int N = in_sizes[2] / 3;               // rays_d is [N,3]
    const int raysPerBlock = (TPB / 32) * 2;     // 8
    const int blocks = (N + raysPerBlock - 1) / raysPerBlock;

    integrate_kernel<<<blocks, TPB>>>(raw, zvals, rays_d, out, N);
}

// round 10
// speedup vs baseline: 1.7177x; 1.2745x over previous
#include <cuda_runtime.h>
#include <math.h>

#define NEARV     2.0f
#define FARV      6.0f
#define FAR_DIST  1e10f
#define S         128
#define TPB       128          // 4 warps, 8 rays per block
#define MAX_BLK   16384
#define FULL      0xffffffffu

// Deterministic scratch for the fused scalar reduction (no allocations allowed).
__device__ float        g_partials[MAX_BLK];
__device__ unsigned int g_count = 0;

__global__ __launch_bounds__(TPB, 1) void integrate_kernel(
    const float* __restrict__ raw,     // [N, S, 4]
    const float* __restrict__ zvals,   // [N, S]
    const float* __restrict__ rays_d,  // [N, 3]
    float* __restrict__ out,           // [3N chs | N depth | 1 scalar]
    int N)
{
    __shared__ float  sh_ent[TPB / 32];
    __shared__ double sh_red[TPB];
    __shared__ bool   sh_last;

    const int warp = threadIdx.x >> 5;
    const int lane = threadIdx.x & 31;
    const int half = lane >> 4;              // 0 -> ray A, 1 -> ray B
    const int l    = lane & 15;              // lane within 16-lane ray group
    int ray = (blockIdx.x * (TPB >> 5) + warp) * 2 + half;
    const bool active = (ray < N);
    if (!active) ray = N - 1;                // clamp: safe reads, stores guarded

    // ---- front-batched fully-coalesced loads: lane owns j = 16k + l ----
    const float4* rp = (const float4*)raw + (size_t)ray * S;
    const float*  zp = zvals + (size_t)ray * S;

    float4 r[8];
    #pragma unroll
    for (int k = 0; k < 8; k++) r[k] = rp[16 * k + l];

    float z[8], zx[8];
    #pragma unroll
    for (int k = 0; k < 8; k++) {
        const int j = 16 * k + l;
        z[k]  = zp[j];
        zx[k] = zp[(j + 1 < S) ? j + 1 : (S - 1)];   // contiguous; L1 hits
    }

    const float* rd = rays_d + (size_t)ray * 3;
    const float nrm = sqrtf(rd[0] * rd[0] + rd[1] * rd[1] + rd[2] * rd[2]);

    // ---- alpha / transmittance factors ----
    float a[8], t[8];
    #pragma unroll
    for (int k = 0; k < 8; k++) {
        const int j = 16 * k + l;
        const float dist = ((j == S - 1) ? FAR_DIST : (zx[k] - z[k])) * nrm;
        const float e = __expf(-fmaxf(r[k].w, 0.0f) * dist);
        a[k] = 1.0f - e;
        t[k] = e + 1e-10f;
    }

    // ---- 8 segmented (width-16) inclusive multiplicative scans ----
    #pragma unroll
    for (int off = 1; off < 16; off <<= 1) {
        #pragma unroll
        for (int k = 0; k < 8; k++) {
            const float v = __shfl_up_sync(FULL, t[k], off, 16);
            if (l >= off) t[k] *= v;
        }
    }

    // exclusive scans + slab totals
    float excl[8], P[8];
    #pragma unroll
    for (int k = 0; k < 8; k++) {
        const float e = __shfl_up_sync(FULL, t[k], 1, 16);
        excl[k] = (l == 0) ? 1.0f : e;
        P[k]    = __shfl_sync(FULL, t[k], 15, 16);
    }

    // ---- weights & accumulation (wz instead of normalized depth) ----
    float c0 = 0.f, c1 = 0.f, c2 = 0.f, wz = 0.f, ws = 0.f, S1 = 0.f;
    float Ck = 1.0f;
    #pragma unroll
    for (int k = 0; k < 8; k++) {
        const float w = a[k] * (Ck * excl[k]);
        c0 += w * r[k].x;
        c1 += w * r[k].y;
        c2 += w * r[k].z;
        wz += w * z[k];
        ws += w;
        if (w > 0.0f) S1 += w * __logf(w);
        Ck *= P[k];
    }

    // ---- packed width-16 reduction: 15 SHFL total for all 6 values ----
    c0 += __shfl_xor_sync(FULL, c0, 8, 16);
    c1 += __shfl_xor_sync(FULL, c1, 8, 16);
    c2 += __shfl_xor_sync(FULL, c2, 8, 16);
    wz += __shfl_xor_sync(FULL, wz, 8, 16);
    ws += __shfl_xor_sync(FULL, ws, 8, 16);
    S1 += __shfl_xor_sync(FULL, S1, 8, 16);
    // lanes l<8 carry {c0,c1,c2}; lanes l>=8 carry {wz,ws,S1}
    float A = (l < 8) ? c0 : wz;
    float B = (l < 8) ? c1 : ws;
    float C = (l < 8) ? c2 : S1;
    #pragma unroll
    for (int off = 4; off > 0; off >>= 1) {
        A += __shfl_xor_sync(FULL, A, off, 16);
        B += __shfl_xor_sync(FULL, B, off, 16);
        C += __shfl_xor_sync(FULL, C, off, 16);
    }
    // lane 0 (and 16): A=Σc0 B=Σc1 C=Σc2 ; lane 8 (and 24): A=Σwz B=Σws C=ΣS1

    float ent = 0.0f;
    if (active && l == 0) {
        out[(size_t)ray * 3 + 0] = A;
        out[(size_t)ray * 3 + 1] = B;
        out[(size_t)ray * 3 + 2] = C;
    }
    if (active && l == 8) {
        const float wzs = A, wss = B, s1s = C;
        // depth = (1.5*ws - 0.25*wz)/(ws+1e-5)
        out[(size_t)3 * N + ray] = (1.5f * wss - 0.25f * wzs) / (wss + 1e-5f);
        // sum p*ln p (p = w/(1+1e-6)) = invD*(S1 + ln(invD)*ws) + tail
        const float invD = 1.0f / (1.0f + 1e-6f);
        ent = invD * (s1s + (-9.999995e-7f) * wss);
        const float p_last = (1.0f - wss + 1e-6f) * invD;
        if (p_last > 0.0f) ent += p_last * __logf(p_last);
    }
    // combine ray A (lane 8) + ray B (lane 24) entropies
    ent += __shfl_xor_sync(FULL, ent, 16);
    if (lane == 8) sh_ent[warp] = ent;
    __syncthreads();

    // ---- fused deterministic grid reduction (threadfence-reduction pattern) ----
    if (threadIdx.x == 0) {
        float s = 0.0f;
        #pragma unroll
        for (int w = 0; w < TPB / 32; w++) s += sh_ent[w];
        g_partials[blockIdx.x] = s;
        __threadfence();
        const unsigned int done = atomicAdd(&g_count, 1u);
        sh_last = (done == gridDim.x - 1);
    }
    __syncthreads();

    if (sh_last) {
        double s = 0.0;
        for (int i = threadIdx.x; i < (int)gridDim.x; i += TPB)
            s += (double)g_partials[i];
        sh_red[threadIdx.x] = s;
        __syncthreads();
        #pragma unroll
        for (int off = TPB / 2; off > 0; off >>= 1) {
            if (threadIdx.x < off) sh_red[threadIdx.x] += sh_red[threadIdx.x + off];
            __syncthreads();
        }
        if (threadIdx.x == 0) {
            out[(size_t)4 * N] = (float)(-sh_red[0]);   // sparsity_loss
            g_count = 0;                                 // re-arm for next replay
        }
    }
}

extern "C" void kernel_launch(void* const* d_in, const int* in_sizes, int n_in,
                              void* d_out, int out_size)
{
    const float* raw    = (const float*)d_in[0];
    const float* zvals  = (const float*)d_in[1];
    const float* rays_d = (const float*)d_in[2];
    float* out = (float*)d_out;

    const int N = in_sizes[2] / 3;               // rays_d is [N,3]
    const int raysPerBlock = (TPB / 32) * 2;     // 8
    const int blocks = (N + raysPerBlock - 1) / raysPerBlock;

    integrate_kernel<<<blocks, TPB>>>(raw, zvals, rays_d, out, N);
}